// round 16
// baseline (speedup 1.0000x reference)
#include <cuda_runtime.h>
#include <cuda_bf16.h>
#include <math.h>
#include <stdint.h>
#include <stddef.h>

#define TSTEPS 1024
#define BATCH  128
#define INDIM  512
#define HID    512
#define GATES  2048   // gate order: i, f, o, g
#define NREC   128    // recurrence blocks (blockIdx 0..127)

// ---------------------------------------------------------------------------
// Device-global scratch
// ---------------------------------------------------------------------------
__device__ float g_xprojT[(size_t)TSTEPS * GATES * BATCH];     // [t][gate][b]
__device__ __nv_bfloat16 g_hhi[2][HID * BATCH];                // h split, [k][b], dbl-buffered
__device__ __nv_bfloat16 g_hlo[2][HID * BATCH];
__device__ __nv_bfloat16 g_xhi[(size_t)TSTEPS * BATCH * INDIM];
__device__ __nv_bfloat16 g_xlo[(size_t)TSTEPS * BATCH * INDIM];
__device__ __nv_bfloat16 g_whi[(size_t)GATES * INDIM];
__device__ __nv_bfloat16 g_wlo[(size_t)GATES * INDIM];
__device__ unsigned g_count;       // init barrier (atomic, self-resetting)
__device__ unsigned g_gen;
__device__ __align__(16) unsigned g_flags[NREC]; // step barrier flags (monotonic)
__device__ unsigned g_genv;        // step barrier release word (monotonic)
__device__ unsigned g_xpcnt[TSTEPS]; // xproj tiles completed per timestep (0..16)

// classic full barrier among the NREC rec blocks (used once after init)
__device__ __forceinline__ void grid_barrier(unsigned nb) {
    __syncthreads();
    if (threadIdx.x == 0) {
        unsigned my = *(volatile unsigned*)&g_gen;
        __threadfence();
        unsigned old = atomicAdd(&g_count, 1u);
        if (old == nb - 1u) {
            atomicExch(&g_count, 0u);
            __threadfence();
            atomicAdd(&g_gen, 1u);
        } else {
            while (*(volatile unsigned*)&g_gen == my) { }
        }
        __threadfence();
    }
    __syncthreads();
}

__device__ __forceinline__ uint32_t smem_u32(const void* p) {
    uint32_t a;
    asm("{ .reg .u64 t; cvta.to.shared.u64 t, %1; cvt.u32.u64 %0, t; }"
        : "=r"(a) : "l"(p));
    return a;
}
#define CP16(dst, src) \
    asm volatile("cp.async.cg.shared.global [%0], [%1], 16;" \
                 :: "r"(dst), "l"(src) : "memory")
#define CP_COMMIT() asm volatile("cp.async.commit_group;" ::: "memory")
#define CP_WAIT(n)  asm volatile("cp.async.wait_group %0;" :: "n"(n) : "memory")

__device__ __forceinline__ void ldm4(uint32_t* r, uint32_t addr) {
    asm volatile("ldmatrix.sync.aligned.m8n8.x4.shared.b16 {%0,%1,%2,%3}, [%4];"
        : "=r"(r[0]), "=r"(r[1]), "=r"(r[2]), "=r"(r[3]) : "r"(addr));
}
__device__ __forceinline__ void ldm4t(uint32_t* r, uint32_t addr) {
    asm volatile("ldmatrix.sync.aligned.m8n8.x4.trans.shared.b16 {%0,%1,%2,%3}, [%4];"
        : "=r"(r[0]), "=r"(r[1]), "=r"(r[2]), "=r"(r[3]) : "r"(addr));
}
__device__ __forceinline__ void mma_bf16(float* c, const uint32_t* a, const uint32_t* b) {
    asm volatile("mma.sync.aligned.m16n8k16.row.col.f32.bf16.bf16.f32 "
        "{%0,%1,%2,%3}, {%4,%5,%6,%7}, {%8,%9}, {%0,%1,%2,%3};"
        : "+f"(c[0]), "+f"(c[1]), "+f"(c[2]), "+f"(c[3])
        : "r"(a[0]), "r"(a[1]), "r"(a[2]), "r"(a[3]), "r"(b[0]), "r"(b[1]));
}

// ---------------------------------------------------------------------------
// Phase 0: split fp32 -> bf16 (hi, lo); split_w also resets xproj counters.
// ---------------------------------------------------------------------------
__global__ void split_x_kernel(const float* __restrict__ src) {
    const int n4 = (TSTEPS * BATCH * INDIM) / 4;
    for (int i = blockIdx.x * blockDim.x + threadIdx.x; i < n4;
         i += gridDim.x * blockDim.x) {
        float4 v = ((const float4*)src)[i];
        __nv_bfloat16 hx = __float2bfloat16(v.x), hy = __float2bfloat16(v.y);
        __nv_bfloat16 hz = __float2bfloat16(v.z), hw = __float2bfloat16(v.w);
        __nv_bfloat162* H = (__nv_bfloat162*)(g_xhi + (size_t)i * 4);
        H[0] = __nv_bfloat162(hx, hy); H[1] = __nv_bfloat162(hz, hw);
        __nv_bfloat162* L = (__nv_bfloat162*)(g_xlo + (size_t)i * 4);
        L[0] = __nv_bfloat162(__float2bfloat16(v.x - __bfloat162float(hx)),
                              __float2bfloat16(v.y - __bfloat162float(hy)));
        L[1] = __nv_bfloat162(__float2bfloat16(v.z - __bfloat162float(hz)),
                              __float2bfloat16(v.w - __bfloat162float(hw)));
    }
}
__global__ void split_w_kernel(const float* __restrict__ src) {
    if (blockIdx.x == 0) {
        for (int i = threadIdx.x; i < TSTEPS; i += blockDim.x) g_xpcnt[i] = 0u;
    }
    const int n4 = (GATES * INDIM) / 4;
    for (int i = blockIdx.x * blockDim.x + threadIdx.x; i < n4;
         i += gridDim.x * blockDim.x) {
        float4 v = ((const float4*)src)[i];
        __nv_bfloat16 hx = __float2bfloat16(v.x), hy = __float2bfloat16(v.y);
        __nv_bfloat16 hz = __float2bfloat16(v.z), hw = __float2bfloat16(v.w);
        __nv_bfloat162* H = (__nv_bfloat162*)(g_whi + (size_t)i * 4);
        H[0] = __nv_bfloat162(hx, hy); H[1] = __nv_bfloat162(hz, hw);
        __nv_bfloat162* L = (__nv_bfloat162*)(g_wlo + (size_t)i * 4);
        L[0] = __nv_bfloat162(__float2bfloat16(v.x - __bfloat162float(hx)),
                              __float2bfloat16(v.y - __bfloat162float(hy)));
        L[1] = __nv_bfloat162(__float2bfloat16(v.z - __bfloat162float(hz)),
                              __float2bfloat16(v.w - __bfloat162float(hw)));
    }
}

// ---------------------------------------------------------------------------
// Fused kernel SMEM maps (dyn smem = 113408 B -> 2 blocks/SM)
// xproj branch:
#define XB_BUF    1024
#define XB_STAGE  40960
#define XB_AH     0
#define XB_AL     10240
#define XB_BH     20480
#define XB_BL     30720
// rec branch:
#define R15_WHI   0                        // 16 rows x 520 halves (1040B)
#define R15_WLO   16640
#define R15_HBUF  33280                    // 4 bufs x (hi 32x272 | lo 32x272)
#define R15_HB(b_) (R15_HBUF + (b_) * 17408)
#define R15_ZS    102912                   // fp32 [16][132]
#define R15_HSTG  111360                   // fp32 [4][128]
#define SMEM_FUSED 113408

// ---------------------------------------------------------------------------
__device__ __forceinline__ void load_xp(float a[2][4], int t, int j0, int n0,
                                        int drow, int dcol) {
    const float* p0 = g_xprojT +
        ((size_t)t * GATES + (drow >> 2) * 512 + j0 + (drow & 3)) * BATCH + n0 + dcol;
    const int r8 = drow + 8;
    const float* p8 = g_xprojT +
        ((size_t)t * GATES + (r8 >> 2) * 512 + j0 + (r8 & 3)) * BATCH + n0 + dcol;
    float2 v;
    v = *(const float2*)(p0);     a[0][0] = v.x; a[0][1] = v.y;
    v = *(const float2*)(p8);     a[0][2] = v.x; a[0][3] = v.y;
    v = *(const float2*)(p0 + 8); a[1][0] = v.x; a[1][1] = v.y;
    v = *(const float2*)(p8 + 8); a[1][2] = v.x; a[1][3] = v.y;
}

// =================== xproj block body (blocks 128..16511) ====================
__device__ void xproj_body(char* sm, uint32_t smb,
                           const float* __restrict__ bih,
                           const float* __restrict__ bhh) {
    float* bias = (float*)sm;
    const int tid = threadIdx.x, wid = tid >> 5, lane = tid & 31;
    const int mw = wid & 1, nw = wid >> 1;
    const int bx = blockIdx.x - NREC;
    const int t  = bx >> 4;
    const int n0 = (bx & 15) * 128;

    if (tid < 128) bias[tid] = bih[n0 + tid] + bhh[n0 + tid];

    float acc[4][4][4];
#pragma unroll
    for (int a = 0; a < 4; a++)
#pragma unroll
        for (int b = 0; b < 4; b++)
#pragma unroll
            for (int q = 0; q < 4; q++) acc[a][b][q] = 0.f;

    const int arow = ((lane >> 3) & 1) * 8 + (lane & 7);
    const int ach  = lane >> 4;
    const int brow = ((lane >> 4) & 1) * 8 + (lane & 7);
    const int bch  = (lane >> 3) & 1;

#define XP_ISSUE(s_, c_) do {                                                  \
    _Pragma("unroll")                                                          \
    for (int j_ = 0; j_ < 2; j_++) {                                           \
        const int u_ = j_ * 256 + tid;                                         \
        const int r_ = u_ >> 2, cc_ = u_ & 3;                                  \
        const size_t gx_ = ((size_t)t * 128 + r_) * INDIM + (c_) * 32 + cc_ * 8; \
        const size_t gw_ = (size_t)(n0 + r_) * INDIM + (c_) * 32 + cc_ * 8;    \
        const uint32_t db_ = smb + XB_BUF + (s_) * XB_STAGE + r_ * 80 + cc_ * 16; \
        CP16(db_ + XB_AH, g_xhi + gx_);                                        \
        CP16(db_ + XB_AL, g_xlo + gx_);                                        \
        CP16(db_ + XB_BH, g_whi + gw_);                                        \
        CP16(db_ + XB_BL, g_wlo + gw_);                                        \
    }                                                                          \
    CP_COMMIT();                                                               \
} while (0)

    XP_ISSUE(0, 0);
#pragma unroll 1
    for (int c = 0; c < 16; c++) {
        if (c < 15) { XP_ISSUE((c + 1) & 1, c + 1); CP_WAIT(1); }
        else        { CP_WAIT(0); }
        __syncthreads();
        const uint32_t base = smb + XB_BUF + (c & 1) * XB_STAGE;
#pragma unroll
        for (int h = 0; h < 2; h++) {
            uint32_t ah[4][4], al[4][4], bhf[2][4], blf[2][4];
#pragma unroll
            for (int mt = 0; mt < 4; mt++) {
                const uint32_t aA = base + XB_AH +
                    (uint32_t)(mw * 64 + mt * 16 + arow) * 80 + (h * 2 + ach) * 16;
                ldm4(ah[mt], aA);
                ldm4(al[mt], aA + (XB_AL - XB_AH));
            }
#pragma unroll
            for (int bt = 0; bt < 2; bt++) {
                const uint32_t aB = base + XB_BH +
                    (uint32_t)(nw * 32 + bt * 16 + brow) * 80 + (h * 2 + bch) * 16;
                ldm4(bhf[bt], aB);
                ldm4(blf[bt], aB + (XB_BL - XB_BH));
            }
#pragma unroll
            for (int mt = 0; mt < 4; mt++)
#pragma unroll
                for (int bt = 0; bt < 2; bt++) {
                    mma_bf16(acc[mt][bt * 2 + 0], ah[mt], bhf[bt] + 0);
                    mma_bf16(acc[mt][bt * 2 + 1], ah[mt], bhf[bt] + 2);
                    mma_bf16(acc[mt][bt * 2 + 0], ah[mt], blf[bt] + 0);
                    mma_bf16(acc[mt][bt * 2 + 1], ah[mt], blf[bt] + 2);
                    mma_bf16(acc[mt][bt * 2 + 0], al[mt], bhf[bt] + 0);
                    mma_bf16(acc[mt][bt * 2 + 1], al[mt], bhf[bt] + 2);
                }
        }
        __syncthreads();
    }

    float* ep = (float*)(sm + XB_BUF);
    const int g = lane >> 2, tg2 = (lane & 3) * 2;
#pragma unroll
    for (int mt = 0; mt < 4; mt++)
#pragma unroll
        for (int nt = 0; nt < 4; nt++) {
            const int bb = mw * 64 + mt * 16 + g;
            const int nn = nw * 32 + nt * 8 + tg2;
            ep[(nn)     * 132 + bb]     = acc[mt][nt][0] + bias[nn];
            ep[(nn + 1) * 132 + bb]     = acc[mt][nt][1] + bias[nn + 1];
            ep[(nn)     * 132 + bb + 8] = acc[mt][nt][2] + bias[nn];
            ep[(nn + 1) * 132 + bb + 8] = acc[mt][nt][3] + bias[nn + 1];
        }
    __syncthreads();
#pragma unroll
    for (int j = 0; j < 16; j++) {
        const int idx = j * 256 + tid;
        const int n = idx >> 5, q = idx & 31;
        const float4 v = *(const float4*)(ep + n * 132 + q * 4);
        *(float4*)(g_xprojT + ((size_t)t * GATES + n0 + n) * BATCH + q * 4) = v;
    }

    // signal: this timestep has one more tile done
    __syncthreads();
    if (tid == 0) {
        __threadfence();
        atomicAdd(&g_xpcnt[t], 1u);
    }
}

// ===================== rec block body (blocks 0..127) ========================
__device__ void rec_body(char* sm, uint32_t smb,
                         const float* __restrict__ Whh, float* __restrict__ out) {
    float* zs   = (float*)(sm + R15_ZS);
    float* hstg = (float*)(sm + R15_HSTG);

    const int tid = threadIdx.x, bid = blockIdx.x;
    const int wid = tid >> 5, lane = tid & 31;
    const int j0 = bid << 2;
    const int n0 = wid << 4;

    // W_hh slice -> SMEM bf16 hi/lo, row m = gt*4+u, stride 520 halves
    for (int i = tid; i < 16 * 512; i += 256) {
        const int m = i >> 9, k = i & 511;
        const int gr = (m >> 2) * 512 + j0 + (m & 3);
        const float w = Whh[(size_t)gr * HID + k];
        const __nv_bfloat16 wh = __float2bfloat16(w);
        ((__nv_bfloat16*)(sm + R15_WHI))[m * 520 + k] = wh;
        ((__nv_bfloat16*)(sm + R15_WLO))[m * 520 + k] =
            __float2bfloat16(w - __bfloat162float(wh));
    }
    // zero h buffer 0 (read at t=0); reset step-barrier state
    {
        const int i = bid * 256 + tid;
        ((uint32_t*)g_hhi[0])[i] = 0u;
        ((uint32_t*)g_hlo[0])[i] = 0u;
    }
    if (bid == 0) {
        if (tid < NREC) g_flags[tid] = 0u;
        if (tid == 0)   *(volatile unsigned*)&g_genv = 0u;
    }
    __threadfence();
    grid_barrier(NREC);

    // lane addressing
    const int arow = ((lane >> 3) & 1) * 8 + (lane & 7);
    const int ach  = lane >> 4;
    const uint32_t aoff = smb + R15_WHI + (uint32_t)arow * 1040 + ach * 16;
    const int krow = ((lane >> 3) & 1) * 8 + (lane & 7);
    const uint32_t bcoloff = (uint32_t)(n0 + (lane >> 4) * 8) * 2;
    const int drow = lane >> 2, dcol = (lane & 3) * 2;

    const int b_ = tid & 127, ug = (tid >> 7) * 2;
    float creg[2] = {0.f, 0.f}, hreg[2] = {0.f, 0.f};

// 32-row chunk copy (16 chunks/step), buffer bb_ of 4
#define REC_ISSUE32(c_, bb_) do {                                              \
    _Pragma("unroll")                                                          \
    for (int j_ = 0; j_ < 2; j_++) {                                           \
        const int u_ = j_ * 256 + tid;                                         \
        const int r_ = u_ >> 4, cc_ = u_ & 15;                                 \
        const uint32_t d_ = smb + R15_HB(bb_) + r_ * 272 + cc_ * 16;           \
        const size_t s_ = hoff + ((size_t)(c_) * 32 + r_) * 128 + cc_ * 8;     \
        CP16(d_, g_hhi[0] + s_);                                               \
        CP16(d_ + 8704, g_hlo[0] + s_);                                        \
    }                                                                          \
    CP_COMMIT();                                                               \
} while (0)

    float accA[2][4];

    for (int t = 0; t < TSTEPS; t++) {
        // wait until all 16 xproj tiles for this timestep are done
        if (tid == 0) {
            while (*(volatile unsigned*)&g_xpcnt[t] < 16u) { }
            __threadfence();
        }
        __syncthreads();

        const size_t hoff = (size_t)(t & 1) * (HID * BATCH);

        load_xp(accA, t, j0, n0, drow, dcol);      // kq0 accumulator init
        float accB[2][4], accC[2][4], accD[2][4];  // k16&3 == 1,2,3
#pragma unroll
        for (int u = 0; u < 2; u++)
#pragma unroll
            for (int v = 0; v < 4; v++) { accB[u][v] = 0.f; accC[u][v] = 0.f; accD[u][v] = 0.f; }

        REC_ISSUE32(0, 0);
        REC_ISSUE32(1, 1);
        REC_ISSUE32(2, 2);
        REC_ISSUE32(3, 3);

#pragma unroll 1
        for (int c = 0; c < 16; c++) {
            const int bb = c & 3;
            if (c < 13)      CP_WAIT(3);
            else if (c == 13) CP_WAIT(2);
            else if (c == 14) CP_WAIT(1);
            else              CP_WAIT(0);
            __syncthreads();
#pragma unroll
            for (int kq2 = 0; kq2 < 2; kq2++) {
                const int k16 = c * 2 + kq2;
                uint32_t ahi[4], alo[4], bhi[4], blo[4];
                ldm4(ahi, aoff + k16 * 32);
                ldm4(alo, aoff + k16 * 32 + (R15_WLO - R15_WHI));
                const uint32_t ba = smb + R15_HB(bb)
                    + (uint32_t)(kq2 * 16 + krow) * 272 + bcoloff;
                ldm4t(bhi, ba);
                ldm4t(blo, ba + 8704);
                const int sel = k16 & 3;
                float (*ax)[4] = (sel == 0) ? accA : (sel == 1) ? accB
                               : (sel == 2) ? accC : accD;
                mma_bf16(ax[0], ahi, bhi + 0);
                mma_bf16(ax[1], ahi, bhi + 2);
                mma_bf16(ax[0], ahi, blo + 0);
                mma_bf16(ax[1], ahi, blo + 2);
                mma_bf16(ax[0], alo, bhi + 0);
                mma_bf16(ax[1], alo, bhi + 2);
            }
            __syncthreads();
            if (c < 12) REC_ISSUE32(c + 4, bb);
        }

        // merge accumulator sets
#pragma unroll
        for (int u = 0; u < 2; u++)
#pragma unroll
            for (int v = 0; v < 4; v++)
                accA[u][v] += (accB[u][v] + accC[u][v]) + accD[u][v];

        // z fragments -> SMEM [m][b]
        {
            const int nc = n0 + dcol;
            *(float2*)&zs[drow * 132 + nc]           = make_float2(accA[0][0], accA[0][1]);
            *(float2*)&zs[(drow + 8) * 132 + nc]     = make_float2(accA[0][2], accA[0][3]);
            *(float2*)&zs[drow * 132 + nc + 8]       = make_float2(accA[1][0], accA[1][1]);
            *(float2*)&zs[(drow + 8) * 132 + nc + 8] = make_float2(accA[1][2], accA[1][3]);
        }
        __syncthreads();

        // gates; publish to parity (t+1)&1
        {
            __nv_bfloat16* dst_hi = g_hhi[(t + 1) & 1];
            __nv_bfloat16* dst_lo = g_hlo[(t + 1) & 1];
#pragma unroll
            for (int q = 0; q < 2; q++) {
                const int u = ug + q;
                const float zi = zs[( 0 + u) * 132 + b_];
                const float zf = zs[( 4 + u) * 132 + b_];
                const float zo = zs[( 8 + u) * 132 + b_];
                const float zg = zs[(12 + u) * 132 + b_];
                const float ig = 1.f / (1.f + expf(-zi));
                const float fg = 1.f / (1.f + expf(-zf));
                const float og = 1.f / (1.f + expf(-zo));
                const float gg = tanhf(zg);
                const float cc = fg * creg[q] + ig * gg;
                creg[q] = cc;
                const float h = og * tanhf(cc);
                hreg[q] = h;
                hstg[u * 128 + b_] = h;
                const __nv_bfloat16 hh = __float2bfloat16(h);
                dst_hi[(j0 + u) * BATCH + b_] = hh;
                dst_lo[(j0 + u) * BATCH + b_] =
                    __float2bfloat16(h - __bfloat162float(hh));
            }
        }
        __syncthreads();

        // ---- flag-tree split barrier: arrive ----
        if (tid == 0) {
            __threadfence();
            *(volatile unsigned*)&g_flags[bid] = (unsigned)(t + 1);
        }

        // overlap window: out-store
        if (tid < 128) {
            const float4 v = make_float4(hstg[0 * 128 + tid], hstg[1 * 128 + tid],
                                         hstg[2 * 128 + tid], hstg[3 * 128 + tid]);
            *(float4*)(out + ((size_t)t * BATCH + tid) * HID + j0) = v;
        }

        // ---- gather (block 0, warp 0) + release ----
        if (bid == 0 && wid == 0) {
            const unsigned tgt = (unsigned)(t + 1);
            for (;;) {
                unsigned f0, f1, f2, f3;
                asm volatile("ld.volatile.global.v4.u32 {%0,%1,%2,%3}, [%4];"
                    : "=r"(f0), "=r"(f1), "=r"(f2), "=r"(f3)
                    : "l"(g_flags + lane * 4));
                const bool ok = (f0 >= tgt) & (f1 >= tgt) & (f2 >= tgt) & (f3 >= tgt);
                if (__all_sync(0xffffffffu, ok)) break;
            }
            if (lane == 0) {
                __threadfence();
                *(volatile unsigned*)&g_genv = tgt;
            }
        }
        // ---- wait ----
        if (tid == 0) {
            while (*(volatile unsigned*)&g_genv < (unsigned)(t + 1)) { }
            __threadfence();
        }
        __syncthreads();
    }

    // final h, c
    {
        const size_t oh = (size_t)TSTEPS * BATCH * HID;
#pragma unroll
        for (int q = 0; q < 2; q++) {
            const int u = ug + q;
            out[oh + (size_t)b_ * HID + j0 + u]                       = hreg[q];
            out[oh + (size_t)BATCH * HID + (size_t)b_ * HID + j0 + u] = creg[q];
        }
    }
}

// ============================ fused kernel ==================================
__global__ __launch_bounds__(256, 2) void fused_kernel(
    const float* __restrict__ Whh, float* __restrict__ out,
    const float* __restrict__ bih, const float* __restrict__ bhh)
{
    extern __shared__ char sm[];
    const uint32_t smb = smem_u32(sm);
    if (blockIdx.x < NREC) rec_body(sm, smb, Whh, out);
    else                   xproj_body(sm, smb, bih, bhh);
}

// ---------------------------------------------------------------------------
extern "C" void kernel_launch(void* const* d_in, const int* in_sizes, int n_in,
                              void* d_out, int out_size) {
    const float* x   = (const float*)d_in[0];
    const float* Wih = (const float*)d_in[1];
    const float* bih = (const float*)d_in[2];
    const float* Whh = (const float*)d_in[3];
    const float* bhh = (const float*)d_in[4];
    float* out = (float*)d_out;
    (void)in_sizes; (void)n_in; (void)out_size;

    split_x_kernel<<<4096, 256>>>(x);
    split_w_kernel<<<512, 256>>>(Wih);

    cudaFuncSetAttribute(fused_kernel,
                         cudaFuncAttributeMaxDynamicSharedMemorySize, SMEM_FUSED);
    fused_kernel<<<NREC + (GATES / 128) * TSTEPS, 256, SMEM_FUSED>>>(
        Whh, out, bih, bhh);
}

// round 17
// speedup vs baseline: 6.4823x; 6.4823x over previous
#include <cuda_runtime.h>
#include <cuda_bf16.h>
#include <cuda_fp16.h>
#include <math.h>
#include <stdint.h>
#include <stddef.h>

#define TSTEPS 1024
#define BATCH  128
#define INDIM  512
#define HID    512
#define GATES  2048   // gate order: i, f, o, g
#define NBLK   128

// ---------------------------------------------------------------------------
// Device-global scratch
// ---------------------------------------------------------------------------
__device__ float g_xprojT[(size_t)TSTEPS * GATES * BATCH];     // [t][gate][b]
__device__ __nv_bfloat16 g_hhi[2][HID * BATCH];                // h split, [k][b], dbl-buffered
__device__ __nv_bfloat16 g_hlo[2][HID * BATCH];
__device__ __half g_xf16[(size_t)TSTEPS * BATCH * INDIM];      // x in fp16 (xproj only)
__device__ __half g_wf16[(size_t)GATES * INDIM];               // W_ih in fp16
__device__ unsigned g_count;       // init barrier (atomic, self-resetting)
__device__ unsigned g_gen;
__device__ __align__(16) unsigned g_flags[NBLK]; // step barrier flags (monotonic)
__device__ unsigned g_genv;        // step barrier release word (monotonic)

// classic full barrier (used once after init; self-resetting)
__device__ __forceinline__ void grid_barrier(unsigned nb) {
    __syncthreads();
    if (threadIdx.x == 0) {
        unsigned my = *(volatile unsigned*)&g_gen;
        __threadfence();
        unsigned old = atomicAdd(&g_count, 1u);
        if (old == nb - 1u) {
            atomicExch(&g_count, 0u);
            __threadfence();
            atomicAdd(&g_gen, 1u);
        } else {
            while (*(volatile unsigned*)&g_gen == my) { }
        }
        __threadfence();
    }
    __syncthreads();
}

__device__ __forceinline__ uint32_t smem_u32(const void* p) {
    uint32_t a;
    asm("{ .reg .u64 t; cvta.to.shared.u64 t, %1; cvt.u32.u64 %0, t; }"
        : "=r"(a) : "l"(p));
    return a;
}
#define CP16(dst, src) \
    asm volatile("cp.async.cg.shared.global [%0], [%1], 16;" \
                 :: "r"(dst), "l"(src) : "memory")
#define CP_COMMIT() asm volatile("cp.async.commit_group;" ::: "memory")
#define CP_WAIT(n)  asm volatile("cp.async.wait_group %0;" :: "n"(n) : "memory")

__device__ __forceinline__ void ldm4(uint32_t* r, uint32_t addr) {
    asm volatile("ldmatrix.sync.aligned.m8n8.x4.shared.b16 {%0,%1,%2,%3}, [%4];"
        : "=r"(r[0]), "=r"(r[1]), "=r"(r[2]), "=r"(r[3]) : "r"(addr));
}
__device__ __forceinline__ void ldm4t(uint32_t* r, uint32_t addr) {
    asm volatile("ldmatrix.sync.aligned.m8n8.x4.trans.shared.b16 {%0,%1,%2,%3}, [%4];"
        : "=r"(r[0]), "=r"(r[1]), "=r"(r[2]), "=r"(r[3]) : "r"(addr));
}
__device__ __forceinline__ void mma_bf16(float* c, const uint32_t* a, const uint32_t* b) {
    asm volatile("mma.sync.aligned.m16n8k16.row.col.f32.bf16.bf16.f32 "
        "{%0,%1,%2,%3}, {%4,%5,%6,%7}, {%8,%9}, {%0,%1,%2,%3};"
        : "+f"(c[0]), "+f"(c[1]), "+f"(c[2]), "+f"(c[3])
        : "r"(a[0]), "r"(a[1]), "r"(a[2]), "r"(a[3]), "r"(b[0]), "r"(b[1]));
}
__device__ __forceinline__ void mma_f16(float* c, const uint32_t* a, const uint32_t* b) {
    asm volatile("mma.sync.aligned.m16n8k16.row.col.f32.f16.f16.f32 "
        "{%0,%1,%2,%3}, {%4,%5,%6,%7}, {%8,%9}, {%0,%1,%2,%3};"
        : "+f"(c[0]), "+f"(c[1]), "+f"(c[2]), "+f"(c[3])
        : "r"(a[0]), "r"(a[1]), "r"(a[2]), "r"(a[3]), "r"(b[0]), "r"(b[1]));
}

// ---------------------------------------------------------------------------
// Phase 0: convert fp32 -> fp16 (single plane; xproj error budget allows it)
// ---------------------------------------------------------------------------
__global__ void split_x_kernel(const float* __restrict__ src) {
    const int n4 = (TSTEPS * BATCH * INDIM) / 4;
    for (int i = blockIdx.x * blockDim.x + threadIdx.x; i < n4;
         i += gridDim.x * blockDim.x) {
        float4 v = ((const float4*)src)[i];
        __half2* H = (__half2*)(g_xf16 + (size_t)i * 4);
        H[0] = __floats2half2_rn(v.x, v.y);
        H[1] = __floats2half2_rn(v.z, v.w);
    }
}
__global__ void split_w_kernel(const float* __restrict__ src) {
    const int n4 = (GATES * INDIM) / 4;
    for (int i = blockIdx.x * blockDim.x + threadIdx.x; i < n4;
         i += gridDim.x * blockDim.x) {
        float4 v = ((const float4*)src)[i];
        __half2* H = (__half2*)(g_wf16 + (size_t)i * 4);
        H[0] = __floats2half2_rn(v.x, v.y);
        H[1] = __floats2half2_rn(v.z, v.w);
    }
}

// ---------------------------------------------------------------------------
// Phase 1: xproj GEMM via single fp16 mma.sync (1 MMA term — 3x fewer than
// the bf16 3-split). CTA tile 128x128, 8 warps (2m x 4n, warp tile 64x32),
// 80B-row SMEM (conflict-free ldmatrix), 2-stage cp.async pipeline, SMEM
// epilogue for coalesced transposed xprojT store.
// ---------------------------------------------------------------------------
#define XB_BUF    1024
#define XB_STAGE  20480              // AH 10240 | BH 10240
#define XB_AH     0
#define XB_BH     10240
#define SMEM_XP   (XB_BUF + 128 * 132 * 4)   // epilogue dominates: 68608 B

__global__ __launch_bounds__(256) void xproj_mma_kernel(
    const float* __restrict__ bih, const float* __restrict__ bhh)
{
    extern __shared__ char sm[];
    const uint32_t smb = smem_u32(sm);
    float* bias = (float*)sm;
    const int tid = threadIdx.x, wid = tid >> 5, lane = tid & 31;
    const int mw = wid & 1, nw = wid >> 1;
    const int t = blockIdx.y;
    const int n0 = blockIdx.x * 128;

    if (tid < 128) bias[tid] = bih[n0 + tid] + bhh[n0 + tid];

    float acc[4][4][4];
#pragma unroll
    for (int a = 0; a < 4; a++)
#pragma unroll
        for (int b = 0; b < 4; b++)
#pragma unroll
            for (int q = 0; q < 4; q++) acc[a][b][q] = 0.f;

    const int arow = ((lane >> 3) & 1) * 8 + (lane & 7);
    const int ach  = lane >> 4;
    const int brow = ((lane >> 4) & 1) * 8 + (lane & 7);
    const int bch  = (lane >> 3) & 1;

#define XP_ISSUE(s_, c_) do {                                                  \
    _Pragma("unroll")                                                          \
    for (int j_ = 0; j_ < 2; j_++) {                                           \
        const int u_ = j_ * 256 + tid;                                         \
        const int r_ = u_ >> 2, cc_ = u_ & 3;                                  \
        const size_t gx_ = ((size_t)t * 128 + r_) * INDIM + (c_) * 32 + cc_ * 8; \
        CP16(smb + XB_BUF + (s_) * XB_STAGE + XB_AH + r_ * 80 + cc_ * 16,      \
             g_xf16 + gx_);                                                    \
    }                                                                          \
    _Pragma("unroll")                                                          \
    for (int j_ = 0; j_ < 2; j_++) {                                           \
        const int u_ = j_ * 256 + tid;                                         \
        const int r_ = u_ >> 2, cc_ = u_ & 3;                                  \
        const size_t gw_ = (size_t)(n0 + r_) * INDIM + (c_) * 32 + cc_ * 8;    \
        CP16(smb + XB_BUF + (s_) * XB_STAGE + XB_BH + r_ * 80 + cc_ * 16,      \
             g_wf16 + gw_);                                                    \
    }                                                                          \
    CP_COMMIT();                                                               \
} while (0)

    XP_ISSUE(0, 0);
#pragma unroll 1
    for (int c = 0; c < 16; c++) {
        if (c < 15) { XP_ISSUE((c + 1) & 1, c + 1); CP_WAIT(1); }
        else        { CP_WAIT(0); }
        __syncthreads();
        const uint32_t base = smb + XB_BUF + (c & 1) * XB_STAGE;
#pragma unroll
        for (int h = 0; h < 2; h++) {
            uint32_t af[4][4], bf[2][4];
#pragma unroll
            for (int mt = 0; mt < 4; mt++)
                ldm4(af[mt], base + XB_AH +
                    (uint32_t)(mw * 64 + mt * 16 + arow) * 80 + (h * 2 + ach) * 16);
#pragma unroll
            for (int bt = 0; bt < 2; bt++)
                ldm4(bf[bt], base + XB_BH +
                    (uint32_t)(nw * 32 + bt * 16 + brow) * 80 + (h * 2 + bch) * 16);
#pragma unroll
            for (int mt = 0; mt < 4; mt++)
#pragma unroll
                for (int bt = 0; bt < 2; bt++) {
                    mma_f16(acc[mt][bt * 2 + 0], af[mt], bf[bt] + 0);
                    mma_f16(acc[mt][bt * 2 + 1], af[mt], bf[bt] + 2);
                }
        }
        __syncthreads();
    }

    float* ep = (float*)(sm + XB_BUF);
    const int g = lane >> 2, tg2 = (lane & 3) * 2;
#pragma unroll
    for (int mt = 0; mt < 4; mt++)
#pragma unroll
        for (int nt = 0; nt < 4; nt++) {
            const int bb = mw * 64 + mt * 16 + g;
            const int nn = nw * 32 + nt * 8 + tg2;
            ep[(nn)     * 132 + bb]     = acc[mt][nt][0] + bias[nn];
            ep[(nn + 1) * 132 + bb]     = acc[mt][nt][1] + bias[nn + 1];
            ep[(nn)     * 132 + bb + 8] = acc[mt][nt][2] + bias[nn];
            ep[(nn + 1) * 132 + bb + 8] = acc[mt][nt][3] + bias[nn + 1];
        }
    __syncthreads();
#pragma unroll
    for (int j = 0; j < 16; j++) {
        const int idx = j * 256 + tid;
        const int n = idx >> 5, q = idx & 31;
        const float4 v = *(const float4*)(ep + n * 132 + q * 4);
        *(float4*)(g_xprojT + ((size_t)t * GATES + n0 + n) * BATCH + q * 4) = v;
    }
}

// ---------------------------------------------------------------------------
// Phase 2: persistent recurrence — R9 VERBATIM (best proven: 9.17us/step).
// ---------------------------------------------------------------------------
#define R6_WHI   0                         // 16 rows x 520 halves (1040B)
#define R6_WLO   16640
#define R6_HBUF  33280                     // 4 bufs x (hi 64x272 | lo 64x272)
#define R6_HB(b_) (R6_HBUF + (b_) * 34816)
#define R6_ZS    172544                    // fp32 [16][132]
#define R6_HSTG  180992                    // fp32 [4][128]
#define SMEM_REC6 183040

__device__ __forceinline__ void load_xp(float a[2][4], int t, int j0, int n0,
                                        int drow, int dcol) {
    const float* p0 = g_xprojT +
        ((size_t)t * GATES + (drow >> 2) * 512 + j0 + (drow & 3)) * BATCH + n0 + dcol;
    const int r8 = drow + 8;
    const float* p8 = g_xprojT +
        ((size_t)t * GATES + (r8 >> 2) * 512 + j0 + (r8 & 3)) * BATCH + n0 + dcol;
    float2 v;
    v = *(const float2*)(p0);     a[0][0] = v.x; a[0][1] = v.y;
    v = *(const float2*)(p8);     a[0][2] = v.x; a[0][3] = v.y;
    v = *(const float2*)(p0 + 8); a[1][0] = v.x; a[1][1] = v.y;
    v = *(const float2*)(p8 + 8); a[1][2] = v.x; a[1][3] = v.y;
}

__global__ __launch_bounds__(256) void rec16_kernel(
    const float* __restrict__ Whh, float* __restrict__ out)
{
    extern __shared__ char sm[];
    const uint32_t smb = smem_u32(sm);
    float* zs   = (float*)(sm + R6_ZS);
    float* hstg = (float*)(sm + R6_HSTG);

    const int tid = threadIdx.x, bid = blockIdx.x;
    const int wid = tid >> 5, lane = tid & 31;
    const int j0 = bid << 2;
    const int n0 = wid << 4;

    // W_hh slice -> SMEM bf16 hi/lo, row m = gt*4+u, stride 520 halves
    for (int i = tid; i < 16 * 512; i += 256) {
        const int m = i >> 9, k = i & 511;
        const int gr = (m >> 2) * 512 + j0 + (m & 3);
        const float w = Whh[(size_t)gr * HID + k];
        const __nv_bfloat16 wh = __float2bfloat16(w);
        ((__nv_bfloat16*)(sm + R6_WHI))[m * 520 + k] = wh;
        ((__nv_bfloat16*)(sm + R6_WLO))[m * 520 + k] =
            __float2bfloat16(w - __bfloat162float(wh));
    }
    // zero h buffer 0 (read at t=0); reset step-barrier state
    {
        const int i = bid * 256 + tid;
        ((uint32_t*)g_hhi[0])[i] = 0u;
        ((uint32_t*)g_hlo[0])[i] = 0u;
    }
    if (bid == 0) {
        if (tid < NBLK) g_flags[tid] = 0u;
        if (tid == 0)   *(volatile unsigned*)&g_genv = 0u;
    }
    __threadfence();
    grid_barrier(NBLK);

    // lane addressing
    const int arow = ((lane >> 3) & 1) * 8 + (lane & 7);
    const int ach  = lane >> 4;
    const uint32_t aoff = smb + R6_WHI + (uint32_t)arow * 1040 + ach * 16;
    const int krow = ((lane >> 3) & 1) * 8 + (lane & 7);
    const uint32_t bcoloff = (uint32_t)(n0 + (lane >> 4) * 8) * 2;
    const int drow = lane >> 2, dcol = (lane & 3) * 2;

    const int b_ = tid & 127, ug = (tid >> 7) * 2;
    float creg[2] = {0.f, 0.f}, hreg[2] = {0.f, 0.f};

#define REC_ISSUE(c_, bb_) do {                                                \
    _Pragma("unroll")                                                          \
    for (int j_ = 0; j_ < 4; j_++) {                                           \
        const int u_ = j_ * 256 + tid;                                         \
        const int r_ = u_ >> 4, cc_ = u_ & 15;                                 \
        const uint32_t d_ = smb + R6_HB(bb_) + r_ * 272 + cc_ * 16;            \
        const size_t s_ = hoff + ((size_t)(c_) * 64 + r_) * 128 + cc_ * 8;     \
        CP16(d_, g_hhi[0] + s_);                                               \
        CP16(d_ + 17408, g_hlo[0] + s_);                                       \
    }                                                                          \
    CP_COMMIT();                                                               \
} while (0)

    float accA[2][4];                         // xproj-initialized, kq==0
    load_xp(accA, 0, j0, n0, drow, dcol);     // prefetch t=0

    for (int t = 0; t < TSTEPS; t++) {
        const size_t hoff = (size_t)(t & 1) * (HID * BATCH);

        float accB[2][4], accC[2][4], accD[2][4];   // kq 1,2,3
#pragma unroll
        for (int u = 0; u < 2; u++)
#pragma unroll
            for (int v = 0; v < 4; v++) { accB[u][v] = 0.f; accC[u][v] = 0.f; accD[u][v] = 0.f; }

        REC_ISSUE(0, 0);
        REC_ISSUE(1, 1);
        REC_ISSUE(2, 2);
        REC_ISSUE(3, 3);

#pragma unroll 1
        for (int c = 0; c < 8; c++) {
            const int bb = c & 3;
            if (c < 5)      CP_WAIT(3);
            else if (c == 5) CP_WAIT(2);
            else if (c == 6) CP_WAIT(1);
            else             CP_WAIT(0);
            __syncthreads();
#pragma unroll
            for (int kq = 0; kq < 4; kq++) {
                const int k16 = c * 4 + kq;
                uint32_t ahi[4], alo[4], bhi[4], blo[4];
                ldm4(ahi, aoff + k16 * 32);
                ldm4(alo, aoff + k16 * 32 + (R6_WLO - R6_WHI));
                const uint32_t ba = smb + R6_HB(bb)
                    + (uint32_t)(kq * 16 + krow) * 272 + bcoloff;
                ldm4t(bhi, ba);
                ldm4t(blo, ba + 17408);
                float (*ax)[4] = (kq == 0) ? accA : (kq == 1) ? accB
                               : (kq == 2) ? accC : accD;
                mma_bf16(ax[0], ahi, bhi + 0);
                mma_bf16(ax[1], ahi, bhi + 2);
                mma_bf16(ax[0], ahi, blo + 0);
                mma_bf16(ax[1], ahi, blo + 2);
                mma_bf16(ax[0], alo, bhi + 0);
                mma_bf16(ax[1], alo, bhi + 2);
            }
            __syncthreads();
            if (c < 4) REC_ISSUE(c + 4, bb);
        }

        // merge accumulator sets
#pragma unroll
        for (int u = 0; u < 2; u++)
#pragma unroll
            for (int v = 0; v < 4; v++)
                accA[u][v] += (accB[u][v] + accC[u][v]) + accD[u][v];

        // z fragments -> SMEM [m][b]
        {
            const int nc = n0 + dcol;
            *(float2*)&zs[drow * 132 + nc]           = make_float2(accA[0][0], accA[0][1]);
            *(float2*)&zs[(drow + 8) * 132 + nc]     = make_float2(accA[0][2], accA[0][3]);
            *(float2*)&zs[drow * 132 + nc + 8]       = make_float2(accA[1][0], accA[1][1]);
            *(float2*)&zs[(drow + 8) * 132 + nc + 8] = make_float2(accA[1][2], accA[1][3]);
        }
        __syncthreads();

        // gates: thread handles (u = ug+q, b = b_); publish to parity (t+1)&1
        {
            __nv_bfloat16* dst_hi = g_hhi[(t + 1) & 1];
            __nv_bfloat16* dst_lo = g_hlo[(t + 1) & 1];
#pragma unroll
            for (int q = 0; q < 2; q++) {
                const int u = ug + q;
                const float zi = zs[( 0 + u) * 132 + b_];
                const float zf = zs[( 4 + u) * 132 + b_];
                const float zo = zs[( 8 + u) * 132 + b_];
                const float zg = zs[(12 + u) * 132 + b_];
                const float ig = 1.f / (1.f + expf(-zi));
                const float fg = 1.f / (1.f + expf(-zf));
                const float og = 1.f / (1.f + expf(-zo));
                const float gg = tanhf(zg);
                const float cc = fg * creg[q] + ig * gg;
                creg[q] = cc;
                const float h = og * tanhf(cc);
                hreg[q] = h;
                hstg[u * 128 + b_] = h;
                const __nv_bfloat16 hh = __float2bfloat16(h);
                dst_hi[(j0 + u) * BATCH + b_] = hh;
                dst_lo[(j0 + u) * BATCH + b_] =
                    __float2bfloat16(h - __bfloat162float(hh));
            }
        }
        __syncthreads();          // hstg + all publishes done block-wide

        // ---- flag-tree split barrier: arrive ----
        if (tid == 0) {
            __threadfence();
            *(volatile unsigned*)&g_flags[bid] = (unsigned)(t + 1);
        }

        // overlap window: out-store + next-step xproj prefetch
        if (tid < 128) {
            const float4 v = make_float4(hstg[0 * 128 + tid], hstg[1 * 128 + tid],
                                         hstg[2 * 128 + tid], hstg[3 * 128 + tid]);
            *(float4*)(out + ((size_t)t * BATCH + tid) * HID + j0) = v;
        }
        if (t + 1 < TSTEPS)
            load_xp(accA, t + 1, j0, n0, drow, dcol);

        // ---- gather (block 0, warp 0) + release ----
        if (bid == 0 && wid == 0) {
            const unsigned tgt = (unsigned)(t + 1);
            for (;;) {
                unsigned f0, f1, f2, f3;
                asm volatile("ld.volatile.global.v4.u32 {%0,%1,%2,%3}, [%4];"
                    : "=r"(f0), "=r"(f1), "=r"(f2), "=r"(f3)
                    : "l"(g_flags + lane * 4));
                const bool ok = (f0 >= tgt) & (f1 >= tgt) & (f2 >= tgt) & (f3 >= tgt);
                if (__all_sync(0xffffffffu, ok)) break;
            }
            if (lane == 0) {
                __threadfence();
                *(volatile unsigned*)&g_genv = tgt;
            }
        }
        // ---- wait ----
        if (tid == 0) {
            while (*(volatile unsigned*)&g_genv < (unsigned)(t + 1)) { }
            __threadfence();
        }
        __syncthreads();
    }

    // final h, c
    {
        const size_t oh = (size_t)TSTEPS * BATCH * HID;
#pragma unroll
        for (int q = 0; q < 2; q++) {
            const int u = ug + q;
            out[oh + (size_t)b_ * HID + j0 + u]                       = hreg[q];
            out[oh + (size_t)BATCH * HID + (size_t)b_ * HID + j0 + u] = creg[q];
        }
    }
}

// ---------------------------------------------------------------------------
extern "C" void kernel_launch(void* const* d_in, const int* in_sizes, int n_in,
                              void* d_out, int out_size) {
    const float* x   = (const float*)d_in[0];
    const float* Wih = (const float*)d_in[1];
    const float* bih = (const float*)d_in[2];
    const float* Whh = (const float*)d_in[3];
    const float* bhh = (const float*)d_in[4];
    float* out = (float*)d_out;
    (void)in_sizes; (void)n_in; (void)out_size;

    split_x_kernel<<<4096, 256>>>(x);
    split_w_kernel<<<512, 256>>>(Wih);

    cudaFuncSetAttribute(xproj_mma_kernel,
                         cudaFuncAttributeMaxDynamicSharedMemorySize, SMEM_XP);
    dim3 g1(GATES / 128, TSTEPS);
    xproj_mma_kernel<<<g1, 256, SMEM_XP>>>(bih, bhh);

    cudaFuncSetAttribute(rec16_kernel,
                         cudaFuncAttributeMaxDynamicSharedMemorySize, SMEM_REC6);
    rec16_kernel<<<NBLK, 256, SMEM_REC6>>>(Whh, out);
}